// round 15
// baseline (speedup 1.0000x reference)
#include <cuda_runtime.h>
#include <cuda_fp16.h>
#include <math.h>
#include <stdint.h>

// ---------------- model constants ----------------
#define BVAL   32
#define DVAL   768
#define NTOK   197
#define NPATCH 196
#define HEADS  12
#define DKV    64
#define MLPD   3072
#define DEPTH  12
#define MTOK   (BVAL*NTOK)     // 6304
#define MPATCH (BVAL*NPATCH)   // 6272
#define SCLD   208             // padded scores row (13*16, 16B-aligned)
#define QKVN   (3*DVAL)        // 2304

// weight-plane offsets (in halves)
#define SZ_ATT  (DEPTH*DVAL*DVAL)
#define SZ_MLP  (DEPTH*DVAL*MLPD)
#define OFF_QKV 0
#define OFF_WO  (3*SZ_ATT)
#define OFF_M1  (4*SZ_ATT)
#define OFF_M2  (4*SZ_ATT + SZ_MLP)
#define OFF_WT  (4*SZ_ATT + 2*SZ_MLP)
#define SZ_ALL  (OFF_WT + DVAL*DVAL)

// ---------------- scratch ----------------
__device__ float g_tok[MTOK*DVAL];
__device__ float g_hbuf[MTOK*DVAL];
__device__ float g_qkv[(long long)MTOK*QKVN];
__device__ float g_ctx[MTOK*DVAL];
__device__ float g_scores[(long long)BVAL*HEADS*NTOK*SCLD];
__device__ float g_hid[(long long)MTOK*MLPD];
__device__ float g_col[(long long)MPATCH*DVAL];
__device__ __half g_bh[SZ_ALL];
__device__ __half g_bl[SZ_ALL];

__device__ __forceinline__ float gelu_f(float x) {
    return 0.5f * x * (1.0f + erff(x * 0.70710678118654752440f));
}

__device__ __forceinline__ void split2(float x, __half& h, __half& l) {
    h = __float2half_rn(x);
    l = __float2half_rn(x - __half2float(h));
}

__device__ __forceinline__ uint32_t smem_u32(const void* p) {
    return (uint32_t)__cvta_generic_to_shared(p);
}

__device__ __forceinline__ void cp16(uint32_t dst, const void* src) {
    asm volatile("cp.async.cg.shared.global [%0], [%1], 16;" :: "r"(dst), "l"(src));
}
#define CP_COMMIT() asm volatile("cp.async.commit_group;")
#define CP_WAIT0()  asm volatile("cp.async.wait_group 0;")
#define CP_WAIT1()  asm volatile("cp.async.wait_group 1;")

__device__ __forceinline__ void ldsm_x4(uint32_t* r, uint32_t addr) {
    asm volatile("ldmatrix.sync.aligned.m8n8.x4.shared.b16 {%0,%1,%2,%3}, [%4];"
                 : "=r"(r[0]), "=r"(r[1]), "=r"(r[2]), "=r"(r[3]) : "r"(addr));
}
__device__ __forceinline__ void ldsm_x4_t(uint32_t* r, uint32_t addr) {
    asm volatile("ldmatrix.sync.aligned.m8n8.x4.trans.shared.b16 {%0,%1,%2,%3}, [%4];"
                 : "=r"(r[0]), "=r"(r[1]), "=r"(r[2]), "=r"(r[3]) : "r"(addr));
}
__device__ __forceinline__ void mma16816(float* c, const uint32_t* a, const uint32_t* b) {
    asm volatile("mma.sync.aligned.m16n8k16.row.col.f32.f16.f16.f32 "
                 "{%0,%1,%2,%3},{%4,%5,%6,%7},{%8,%9},{%0,%1,%2,%3};"
                 : "+f"(c[0]), "+f"(c[1]), "+f"(c[2]), "+f"(c[3])
                 : "r"(a[0]), "r"(a[1]), "r"(a[2]), "r"(a[3]), "r"(b[0]), "r"(b[1]));
}

// =========================================================================
// fp16-split (3-term) tensor-core GEMM: 128x128 tile, 256 thr, occ 2,
// KC=32. A fp32 via LDG + in-kernel split (reg double-buffer, L1 reuse).
// B pre-split planes via cp.async, 3-stage ring with wait_group 1 (two
// iterations of flight). Split-K aware.
// EPI: 0=store; 2=gelu(acc+bias); 3=C+=; 5=atomicAdd (+bias chunk0)
// =========================================================================
#define ASTR 40
#define BSTR 136
#define A_PL (128*ASTR)
#define B_PL (32*BSTR)
#define SMEM_HS ((4*A_PL + 6*B_PL) * 2)   // 93184 bytes

template<int EPI>
__global__ __launch_bounds__(256, 2)
void hsgemm_kernel(int M, int N, int K,
                   const float* __restrict__ A, int lda,
                   const __half* __restrict__ Bh, const __half* __restrict__ Bl, int ldb,
                   float* __restrict__ C, int ldc,
                   const float* __restrict__ bias)
{
    extern __shared__ __half sm[];
    __half* Ahs = sm;                    // [2][A_PL]
    __half* Als = sm + 2 * A_PL;
    __half* Bhs = sm + 4 * A_PL;         // [3][B_PL]
    __half* Bls = sm + 4 * A_PL + 3 * B_PL;

    const int tid = threadIdx.x;
    const int lane = tid & 31, wid = tid >> 5;
    const int warpM = wid >> 2, warpN = wid & 3;
    const int quad = lane & 3, gid = lane >> 2;
    const int row0 = blockIdx.y * 128, col0 = blockIdx.x * 128;

    const int kLen = K / gridDim.z;
    const int zoff = blockIdx.z * kLen;
    A  += zoff;
    Bh += (size_t)zoff * ldb;
    Bl += (size_t)zoff * ldb;

    float acc[4][4][4];
    #pragma unroll
    for (int i = 0; i < 4; i++)
        #pragma unroll
        for (int j = 0; j < 4; j++)
            #pragma unroll
            for (int r = 0; r < 4; r++) acc[i][j][r] = 0.f;

    int aR[4], aC[4];
    #pragma unroll
    for (int i = 0; i < 4; i++) {
        int e = tid + i * 256;
        aR[i] = e >> 3;  aC[i] = (e & 7) * 4;
    }
    int bRow[2], bCg[2];
    #pragma unroll
    for (int i = 0; i < 2; i++) {
        int c = tid + i * 256;
        bRow[i] = c >> 4; bCg[i] = (c & 15) * 8;
    }

    const int nk = kLen / 32;
    float4 va[4];

    // ---- prologue: B stages 0,1 in flight; A stage 0 in smem ----
    #pragma unroll
    for (int i = 0; i < 2; i++) {
        uint32_t db = (uint32_t)((bRow[i] * BSTR + bCg[i]) * 2);
        cp16(smem_u32(Bhs) + db, Bh + (size_t)bRow[i] * ldb + col0 + bCg[i]);
        cp16(smem_u32(Bls) + db, Bl + (size_t)bRow[i] * ldb + col0 + bCg[i]);
    }
    CP_COMMIT();
    if (nk > 1) {
        #pragma unroll
        for (int i = 0; i < 2; i++) {
            uint32_t db = (uint32_t)((B_PL + bRow[i] * BSTR + bCg[i]) * 2);
            cp16(smem_u32(Bhs) + db, Bh + (size_t)(32 + bRow[i]) * ldb + col0 + bCg[i]);
            cp16(smem_u32(Bls) + db, Bl + (size_t)(32 + bRow[i]) * ldb + col0 + bCg[i]);
        }
    }
    CP_COMMIT();
    #pragma unroll
    for (int i = 0; i < 4; i++) {
        int gm = row0 + aR[i];
        va[i] = (gm < M) ? *(const float4*)(A + (size_t)gm * lda + aC[i])
                         : make_float4(0.f, 0.f, 0.f, 0.f);
    }
    #pragma unroll
    for (int i = 0; i < 4; i++) {
        __half h0,h1,h2,h3,l0,l1,l2,l3;
        split2(va[i].x,h0,l0); split2(va[i].y,h1,l1);
        split2(va[i].z,h2,l2); split2(va[i].w,h3,l3);
        __half2* ph = (__half2*)&Ahs[aR[i]*ASTR + aC[i]];
        ph[0] = __halves2half2(h0,h1); ph[1] = __halves2half2(h2,h3);
        __half2* pl = (__half2*)&Als[aR[i]*ASTR + aC[i]];
        pl[0] = __halves2half2(l0,l1); pl[1] = __halves2half2(l2,l3);
    }
    CP_WAIT1();           // stage 0 complete (stage 1 may still be in flight)
    __syncthreads();

    for (int kt = 0; kt < nk; kt++) {
        const int curA = kt & 1;
        const int curB = kt % 3;
        const bool more = (kt + 1 < nk);

        // prefetch B two iterations ahead (empty commit keeps group count exact)
        if (kt + 2 < nk) {
            const int k0 = (kt + 2) * 32;
            const int pB = (kt + 2) % 3;
            #pragma unroll
            for (int i = 0; i < 2; i++) {
                uint32_t db = (uint32_t)((pB * B_PL + bRow[i] * BSTR + bCg[i]) * 2);
                cp16(smem_u32(Bhs) + db, Bh + (size_t)(k0 + bRow[i]) * ldb + col0 + bCg[i]);
                cp16(smem_u32(Bls) + db, Bl + (size_t)(k0 + bRow[i]) * ldb + col0 + bCg[i]);
            }
        }
        CP_COMMIT();

        if (more) {
            const int k0 = (kt + 1) * 32;
            #pragma unroll
            for (int i = 0; i < 4; i++) {
                int gm = row0 + aR[i];
                va[i] = (gm < M) ? *(const float4*)(A + (size_t)gm * lda + k0 + aC[i])
                                 : make_float4(0.f, 0.f, 0.f, 0.f);
            }
        }

        // ---- compute on A stage curA, B stage curB ----
        #pragma unroll
        for (int ks = 0; ks < 32; ks += 16) {
            uint32_t ah[4][4], al[4][4], bh[4][2], bl[4][2];
            const uint32_t aoff = (uint32_t)((curA * A_PL + (lane & 15) * ASTR + ks + (lane >> 4) * 8) * 2);
            const uint32_t ah_base = smem_u32(Ahs) + aoff;
            const uint32_t al_base = smem_u32(Als) + aoff;
            #pragma unroll
            for (int mi = 0; mi < 4; mi++) {
                uint32_t o = (uint32_t)((warpM * 64 + mi * 16) * ASTR * 2);
                ldsm_x4(ah[mi], ah_base + o);
                ldsm_x4(al[mi], al_base + o);
            }
            const uint32_t boff = (uint32_t)((curB * B_PL + (ks + (lane & 15)) * BSTR + (lane >> 4) * 8) * 2);
            const uint32_t bh_base = smem_u32(Bhs) + boff;
            const uint32_t bl_base = smem_u32(Bls) + boff;
            #pragma unroll
            for (int np = 0; np < 2; np++) {
                uint32_t o = (uint32_t)((warpN * 32 + np * 16) * 2);
                uint32_t r[4];
                ldsm_x4_t(r, bh_base + o);
                bh[np*2][0] = r[0]; bh[np*2][1] = r[1];
                bh[np*2+1][0] = r[2]; bh[np*2+1][1] = r[3];
                ldsm_x4_t(r, bl_base + o);
                bl[np*2][0] = r[0]; bl[np*2][1] = r[1];
                bl[np*2+1][0] = r[2]; bl[np*2+1][1] = r[3];
            }
            #pragma unroll
            for (int mi = 0; mi < 4; mi++)
                #pragma unroll
                for (int ni = 0; ni < 4; ni++) {
                    mma16816(acc[mi][ni], ah[mi], bh[ni]);
                    mma16816(acc[mi][ni], ah[mi], bl[ni]);
                    mma16816(acc[mi][ni], al[mi], bh[ni]);
                }
        }

        if (more) {
            const int nxtA = curA ^ 1;
            #pragma unroll
            for (int i = 0; i < 4; i++) {
                __half h0,h1,h2,h3,l0,l1,l2,l3;
                split2(va[i].x,h0,l0); split2(va[i].y,h1,l1);
                split2(va[i].z,h2,l2); split2(va[i].w,h3,l3);
                __half2* ph = (__half2*)&Ahs[nxtA*A_PL + aR[i]*ASTR + aC[i]];
                ph[0] = __halves2half2(h0,h1); ph[1] = __halves2half2(h2,h3);
                __half2* pl = (__half2*)&Als[nxtA*A_PL + aR[i]*ASTR + aC[i]];
                pl[0] = __halves2half2(l0,l1); pl[1] = __halves2half2(l2,l3);
            }
            CP_WAIT1();       // stage kt+1 complete (kt+2 may still fly)
            __syncthreads();
        }
    }

    const bool addBias = (EPI == 2 || EPI == 3) || (EPI == 5 && blockIdx.z == 0 && bias != nullptr);
    #pragma unroll
    for (int mi = 0; mi < 4; mi++) {
        int rr[2];
        rr[0] = row0 + warpM * 64 + mi * 16 + gid;
        rr[1] = rr[0] + 8;
        #pragma unroll
        for (int ni = 0; ni < 4; ni++) {
            int c = col0 + warpN * 32 + ni * 8 + 2 * quad;
            float b0 = 0.f, b1 = 0.f;
            if (EPI >= 2 && addBias) { b0 = bias[c]; b1 = bias[c + 1]; }
            #pragma unroll
            for (int h = 0; h < 2; h++) {
                if (rr[h] >= M) continue;
                float x0 = acc[mi][ni][2*h]     + b0;
                float x1 = acc[mi][ni][2*h + 1] + b1;
                if (EPI == 2) { x0 = gelu_f(x0); x1 = gelu_f(x1); }
                size_t idx = (size_t)rr[h] * ldc + c;
                if (EPI == 3)      { C[idx] += x0; C[idx + 1] += x1; }
                else if (EPI == 5) { atomicAdd(&C[idx], x0); atomicAdd(&C[idx + 1], x1); }
                else               { C[idx] = x0;  C[idx + 1] = x1; }
            }
        }
    }
}

static void launch_hs(int epi, int M, int N, int K,
                      const float* A, int lda,
                      const __half* Bh, const __half* Bl, int ldb,
                      float* C, int ldc, const float* bias, int splits = 1)
{
    dim3 grid(N / 128, (M + 127) / 128, splits), blk(256);
    if      (epi == 0) hsgemm_kernel<0><<<grid, blk, SMEM_HS>>>(M, N, K, A, lda, Bh, Bl, ldb, C, ldc, bias);
    else if (epi == 2) hsgemm_kernel<2><<<grid, blk, SMEM_HS>>>(M, N, K, A, lda, Bh, Bl, ldb, C, ldc, bias);
    else if (epi == 3) hsgemm_kernel<3><<<grid, blk, SMEM_HS>>>(M, N, K, A, lda, Bh, Bl, ldb, C, ldc, bias);
    else               hsgemm_kernel<5><<<grid, blk, SMEM_HS>>>(M, N, K, A, lda, Bh, Bl, ldb, C, ldc, bias);
}

// =========================================================================
// scores GEMM: QK^T, tile 128(M) x 128(N), 8 warps 2x4 (64x32 warp tiles),
// both operands via float4 staging + in-kernel split. K=64 (4 k-iters).
// =========================================================================
#define ASTR3 24
#define BSTR3 136

__global__ __launch_bounds__(256)
void scores_gemm(int M, int N, int K,
                 const float* __restrict__ A, int lda, long long sA0, long long sA1,
                 const float* __restrict__ B, int ldb, long long sB0, long long sB1,
                 float* __restrict__ C, int ldc, long long sC0, long long sC1,
                 int hdiv)
{
    __shared__ __align__(16) __half As[2][128 * ASTR3];
    __shared__ __align__(16) __half Bs[2][16 * BSTR3];

    const int z = blockIdx.z;
    const int zb = z / hdiv, zh = z - zb * hdiv;
    A += zb * sA0 + zh * sA1;
    B += zb * sB0 + zh * sB1;
    C += zb * sC0 + zh * sC1;

    const int tid = threadIdx.x;
    const int lane = tid & 31, wid = tid >> 5;
    const int warpM = wid >> 2, warpN = wid & 3;
    const int quad = lane & 3, gid = lane >> 2;
    const int row0 = blockIdx.y * 128, col0 = blockIdx.x * 128;

    float acc[4][4][4];
    #pragma unroll
    for (int i = 0; i < 4; i++)
        #pragma unroll
        for (int j = 0; j < 4; j++)
            #pragma unroll
            for (int r = 0; r < 4; r++) acc[i][j][r] = 0.f;

    const int nk = K / 16;   // 4

    for (int kt = 0; kt < nk; kt++) {
        const int k0 = kt * 16;
        #pragma unroll
        for (int i = 0; i < 2; i++) {
            int e = tid + i * 256;
            int ar = e >> 2, ac = (e & 3) * 4;
            int gm = row0 + ar;
            float4 v = (gm < M) ? *(const float4*)(A + (size_t)gm * lda + k0 + ac)
                                : make_float4(0.f, 0.f, 0.f, 0.f);
            __half h0,h1,h2,h3,l0,l1,l2,l3;
            split2(v.x,h0,l0); split2(v.y,h1,l1);
            split2(v.z,h2,l2); split2(v.w,h3,l3);
            __half2* ph = (__half2*)&As[0][ar * ASTR3 + ac];
            ph[0] = __halves2half2(h0,h1); ph[1] = __halves2half2(h2,h3);
            __half2* pl = (__half2*)&As[1][ar * ASTR3 + ac];
            pl[0] = __halves2half2(l0,l1); pl[1] = __halves2half2(l2,l3);
        }
        #pragma unroll
        for (int i = 0; i < 2; i++) {
            int e = tid + i * 256;
            int nr = e >> 2, kc = (e & 3) * 4;
            int gn = col0 + nr;
            float4 v = (gn < N) ? *(const float4*)(B + (size_t)gn * ldb + k0 + kc)
                                : make_float4(0.f, 0.f, 0.f, 0.f);
            float vv[4] = {v.x, v.y, v.z, v.w};
            #pragma unroll
            for (int j = 0; j < 4; j++) {
                __half h, l; split2(vv[j], h, l);
                Bs[0][(kc + j) * BSTR3 + nr] = h;
                Bs[1][(kc + j) * BSTR3 + nr] = l;
            }
        }
        __syncthreads();

        {
            uint32_t ah[4][4], al[4][4], bh[4][2], bl[4][2];
            const uint32_t aoff = (uint32_t)(((lane & 15) * ASTR3 + (lane >> 4) * 8) * 2);
            const uint32_t ah_base = smem_u32(&As[0][0]) + aoff;
            const uint32_t al_base = smem_u32(&As[1][0]) + aoff;
            #pragma unroll
            for (int mi = 0; mi < 4; mi++) {
                uint32_t o = (uint32_t)((warpM * 64 + mi * 16) * ASTR3 * 2);
                ldsm_x4(ah[mi], ah_base + o);
                ldsm_x4(al[mi], al_base + o);
            }
            const uint32_t boff = (uint32_t)(((lane & 15) * BSTR3 + (lane >> 4) * 8) * 2);
            const uint32_t bh_base = smem_u32(&Bs[0][0]) + boff;
            const uint32_t bl_base = smem_u32(&Bs[1][0]) + boff;
            #pragma unroll
            for (int np = 0; np < 2; np++) {
                uint32_t o = (uint32_t)((warpN * 32 + np * 16) * 2);
                uint32_t r[4];
                ldsm_x4_t(r, bh_base + o);
                bh[np*2][0] = r[0]; bh[np*2][1] = r[1];
                bh[np*2+1][0] = r[2]; bh[np*2+1][1] = r[3];
                ldsm_x4_t(r, bl_base + o);
                bl[np*2][0] = r[0]; bl[np*2][1] = r[1];
                bl[np*2+1][0] = r[2]; bl[np*2+1][1] = r[3];
            }
            #pragma unroll
            for (int mi = 0; mi < 4; mi++)
                #pragma unroll
                for (int ni = 0; ni < 4; ni++) {
                    mma16816(acc[mi][ni], ah[mi], bh[ni]);
                    mma16816(acc[mi][ni], ah[mi], bl[ni]);
                    mma16816(acc[mi][ni], al[mi], bh[ni]);
                }
        }
        __syncthreads();
    }

    #pragma unroll
    for (int mi = 0; mi < 4; mi++) {
        int rr[2];
        rr[0] = row0 + warpM * 64 + mi * 16 + gid;
        rr[1] = rr[0] + 8;
        #pragma unroll
        for (int ni = 0; ni < 4; ni++) {
            int c = col0 + warpN * 32 + ni * 8 + 2 * quad;
            #pragma unroll
            for (int h = 0; h < 2; h++) {
                if (rr[h] >= M) continue;
                size_t idx = (size_t)rr[h] * ldc + c;
                if (c < N)     C[idx]     = acc[mi][ni][2*h];
                if (c + 1 < N) C[idx + 1] = acc[mi][ni][2*h + 1];
            }
        }
    }
}

// =========================================================================
// ctx GEMM (attn @ V): tile 128(M) x 64(N). A (scores, ld=SCLD, zero-padded
// cols) staged via float4; V staged scalar with real kv bound (NTOK).
// =========================================================================
#define ASTR2 24
#define BSTR2 72

__global__ __launch_bounds__(256)
void ctx_gemm(int M, int N,
              const float* __restrict__ A, long long sA0, long long sA1,
              const float* __restrict__ B, int ldb, long long sB0, long long sB1,
              float* __restrict__ C, int ldc, long long sC0, long long sC1,
              int hdiv)
{
    __shared__ __align__(16) __half As[2][128 * ASTR2];
    __shared__ __align__(16) __half Bs[2][16 * BSTR2];

    const int z = blockIdx.z;
    const int zb = z / hdiv, zh = z - zb * hdiv;
    A += zb * sA0 + zh * sA1;
    B += zb * sB0 + zh * sB1;
    C += zb * sC0 + zh * sC1;

    const int tid = threadIdx.x;
    const int lane = tid & 31, wid = tid >> 5;
    const int warpM = wid >> 1, warpN = wid & 1;
    const int quad = lane & 3, gid = lane >> 2;
    const int row0 = blockIdx.y * 128, col0 = blockIdx.x * 64;

    float acc[2][4][4];
    #pragma unroll
    for (int i = 0; i < 2; i++)
        #pragma unroll
        for (int j = 0; j < 4; j++)
            #pragma unroll
            for (int r = 0; r < 4; r++) acc[i][j][r] = 0.f;

    const int nk = SCLD / 16;   // 13

    for (int kt = 0; kt < nk; kt++) {
        const int k0 = kt * 16;
        #pragma unroll
        for (int i = 0; i < 2; i++) {
            int e = tid + i * 256;
            int ar = e >> 2, ac = (e & 3) * 4;
            int gm = row0 + ar;
            float4 v = (gm < M) ? *(const float4*)(A + (size_t)gm * SCLD + k0 + ac)
                                : make_float4(0.f, 0.f, 0.f, 0.f);
            __half h0,h1,h2,h3,l0,l1,l2,l3;
            split2(v.x,h0,l0); split2(v.y,h1,l1);
            split2(v.z,h2,l2); split2(v.w,h3,l3);
            __half2* ph = (__half2*)&As[0][ar * ASTR2 + ac];
            ph[0] = __halves2half2(h0,h1); ph[1] = __halves2half2(h2,h3);
            __half2* pl = (__half2*)&As[1][ar * ASTR2 + ac];
            pl[0] = __halves2half2(l0,l1); pl[1] = __halves2half2(l2,l3);
        }
        {
            int kl = tid >> 4, nc = (tid & 15) * 4;
            int gk = k0 + kl;
            #pragma unroll
            for (int j = 0; j < 4; j++) {
                int gn = col0 + nc + j;
                float v = (gk < NTOK && gn < N) ? B[(size_t)gk * ldb + gn] : 0.f;
                __half h, l; split2(v, h, l);
                Bs[0][kl * BSTR2 + nc + j] = h;
                Bs[1][kl * BSTR2 + nc + j] = l;
            }
        }
        __syncthreads();

        {
            uint32_t ah[2][4], al[2][4], bh[4][2], bl[4][2];
            const uint32_t aoff = (uint32_t)(((lane & 15) * ASTR2 + (lane >> 4) * 8) * 2);
            const uint32_t ah_base = smem_u32(&As[0][0]) + aoff;
            const uint32_t al_base = smem_u32(&As[1][0]) + aoff;
            #pragma unroll
            for (int mi = 0; mi < 2; mi++) {
                uint32_t o = (uint32_t)((warpM * 32 + mi * 16) * ASTR2 * 2);
                ldsm_x4(ah[mi], ah_base + o);
                ldsm_x4(al[mi], al_base + o);
            }
            const uint32_t boff = (uint32_t)(((lane & 15) * BSTR2 + (lane >> 4) * 8) * 2);
            const uint32_t bh_base = smem_u32(&Bs[0][0]) + boff;
            const uint32_t bl_base = smem_u32(&Bs[1][0]) + boff;
            #pragma unroll
            for (int np = 0; np < 2; np++) {
                uint32_t o = (uint32_t)((warpN * 32 + np * 16) * 2);
                uint32_t r[4];
                ldsm_x4_t(r, bh_base + o);
                bh[np*2][0] = r[0]; bh[np*2][1] = r[1];
                bh[np*2+1][0] = r[2]; bh[np*2+1][1] = r[3];
                ldsm_x4_t(r, bl_base + o);
                bl[np*2][0] = r[0]; bl[np*2][1] = r[1];
                bl[np*2+1][0] = r[2]; bl[np*2+1][1] = r[3];
            }
            #pragma unroll
            for (int mi = 0; mi < 2; mi++)
                #pragma unroll
                for (int ni = 0; ni < 4; ni++) {
                    mma16816(acc[mi][ni], ah[mi], bh[ni]);
                    mma16816(acc[mi][ni], ah[mi], bl[ni]);
                    mma16816(acc[mi][ni], al[mi], bh[ni]);
                }
        }
        __syncthreads();
    }

    #pragma unroll
    for (int mi = 0; mi < 2; mi++) {
        int rr[2];
        rr[0] = row0 + warpM * 32 + mi * 16 + gid;
        rr[1] = rr[0] + 8;
        #pragma unroll
        for (int ni = 0; ni < 4; ni++) {
            int c = col0 + warpN * 32 + ni * 8 + 2 * quad;
            #pragma unroll
            for (int h = 0; h < 2; h++) {
                if (rr[h] >= M) continue;
                size_t idx = (size_t)rr[h] * ldc + c;
                if (c < N)     C[idx]     = acc[mi][ni][2*h];
                if (c + 1 < N) C[idx + 1] = acc[mi][ni][2*h + 1];
            }
        }
    }
}

// =========================================================================
// mega weight split (QKV packed + wo + mlp1 + mlp2 + convT)
// =========================================================================
__global__ void split_all_kernel(const float* __restrict__ wq, const float* __restrict__ wk,
                                 const float* __restrict__ wv, const float* __restrict__ wo,
                                 const float* __restrict__ m1, const float* __restrict__ m2,
                                 const float* __restrict__ cw,
                                 __half* __restrict__ bh, __half* __restrict__ bl)
{
    const long long QKV4 = 3LL * SZ_ATT / 4;
    const long long WO4  = (long long)SZ_ATT / 4;
    const long long M4   = (long long)SZ_MLP / 4;
    const long long TOT4 = QKV4 + WO4 + 2 * M4;

    long long i = (long long)blockIdx.x * 256 + threadIdx.x;

    if (i < QKV4) {
        int w = (int)(i / (SZ_ATT / 4));
        long long j = i - (long long)w * (SZ_ATT / 4);
        const float* src = (w == 0) ? wq : (w == 1) ? wk : wv;
        float4 v = ((const float4*)src)[j];
        long long s = 4 * j;
        int L = (int)(s / ((long long)DVAL * DVAL));
        int r = (int)(s - (long long)L * DVAL * DVAL);
        int k = r / DVAL, n = r - k * DVAL;
        long long d = OFF_QKV + (long long)L * DVAL * QKVN + (long long)k * QKVN + w * DVAL + n;
        __half h0,h1,h2,h3,l0,l1,l2,l3;
        split2(v.x,h0,l0); split2(v.y,h1,l1); split2(v.z,h2,l2); split2(v.w,h3,l3);
        __half2* ph = (__half2*)(bh + d);
        ph[0] = __halves2half2(h0,h1); ph[1] = __halves2half2(h2,h3);
        __half2* pl = (__half2*)(bl + d);
        pl[0] = __halves2half2(l0,l1); pl[1] = __halves2half2(l2,l3);
        return;
    }
    if (i < TOT4) {
        long long i2 = i - QKV4;
        const float* src; long long off, j;
        if (i2 < WO4)            { src = wo; off = OFF_WO; j = i2; }
        else if (i2 < WO4 + M4)  { src = m1; off = OFF_M1; j = i2 - WO4; }
        else                     { src = m2; off = OFF_M2; j = i2 - WO4 - M4; }
        float4 v = ((const float4*)src)[j];
        long long d = off + 4 * j;
        __half h0,h1,h2,h3,l0,l1,l2,l3;
        split2(v.x,h0,l0); split2(v.y,h1,l1); split2(v.z,h2,l2); split2(v.w,h3,l3);
        __half2* ph = (__half2*)(bh + d);
        ph[0] = __halves2half2(h0,h1); ph[1] = __halves2half2(h2,h3);
        __half2* pl = (__half2*)(bl + d);
        pl[0] = __halves2half2(l0,l1); pl[1] = __halves2half2(l2,l3);
        return;
    }
    long long idx = i - TOT4;
    if (idx < (long long)DVAL * DVAL) {
        int k = (int)(idx / DVAL), n = (int)(idx % DVAL);
        float x = cw[(long long)n * DVAL + k];
        __half h, l; split2(x, h, l);
        bh[OFF_WT + idx] = h;
        bl[OFF_WT + idx] = l;
    }
}

// ---------------- LayerNorm (warp-shuffle reductions) ----------------
__global__ void ln_kernel(const float* __restrict__ in, float* __restrict__ out,
                          const float* __restrict__ w, const float* __restrict__ b)
{
    __shared__ float red[8];
    int row = blockIdx.x;
    int tid = threadIdx.x;
    int lane = tid & 31, wd = tid >> 5;
    const float* x = in + (long long)row * DVAL;

    float v0 = x[tid], v1 = x[tid + 256], v2 = x[tid + 512];
    float s = v0 + v1 + v2;
    #pragma unroll
    for (int o = 16; o > 0; o >>= 1) s += __shfl_xor_sync(0xffffffffu, s, o);
    if (lane == 0) red[wd] = s;
    __syncthreads();
    float mu = (red[0] + red[1] + red[2] + red[3] + red[4] + red[5] + red[6] + red[7])
               * (1.0f / 768.0f);

    float d0 = v0 - mu, d1 = v1 - mu, d2 = v2 - mu;
    float s2 = d0 * d0 + d1 * d1 + d2 * d2;
    #pragma unroll
    for (int o = 16; o > 0; o >>= 1) s2 += __shfl_xor_sync(0xffffffffu, s2, o);
    __syncthreads();
    if (lane == 0) red[wd] = s2;
    __syncthreads();
    float rs = rsqrtf((red[0] + red[1] + red[2] + red[3] + red[4] + red[5] + red[6] + red[7])
                      * (1.0f / 768.0f) + 1e-5f);

    float* y = out + (long long)row * DVAL;
    y[tid]       = d0 * rs * w[tid]       + b[tid];
    y[tid + 256] = d1 * rs * w[tid + 256] + b[tid + 256];
    y[tid + 512] = d2 * rs * w[tid + 512] + b[tid + 512];
}

// ---------------- softmax (rows of SCLD; zero pad cols 197..207) ----------------
__global__ void softmax_kernel(float* __restrict__ s)
{
    int row = blockIdx.x * 8 + (threadIdx.x >> 5);
    if (row >= BVAL * HEADS * NTOK) return;
    int lane = threadIdx.x & 31;
    float* p = s + (long long)row * SCLD;
    const float scale = 0.125f;

    float vals[7];
    float mx = -1e30f;
    #pragma unroll
    for (int i = 0; i < 7; i++) {
        int c = lane + i * 32;
        float v = (c < NTOK) ? p[c] * scale : -1e30f;
        vals[i] = v;
        mx = fmaxf(mx, v);
    }
    #pragma unroll
    for (int o = 16; o > 0; o >>= 1) mx = fmaxf(mx, __shfl_xor_sync(0xffffffffu, mx, o));

    float sum = 0.f;
    #pragma unroll
    for (int i = 0; i < 7; i++) {
        int c = lane + i * 32;
        float e = (c < NTOK) ? expf(vals[i] - mx) : 0.f;
        vals[i] = e;
        sum += e;
    }
    #pragma unroll
    for (int o = 16; o > 0; o >>= 1) sum += __shfl_xor_sync(0xffffffffu, sum, o);
    float inv = 1.0f / sum;

    #pragma unroll
    for (int i = 0; i < 7; i++) {
        int c = lane + i * 32;
        if (c < NTOK)      p[c] = vals[i] * inv;
        else if (c < SCLD) p[c] = 0.f;
    }
}

// ---------------- patch-embed helpers ----------------
__global__ void im2col_kernel(const float* __restrict__ x)
{
    long long idx = (long long)blockIdx.x * blockDim.x + threadIdx.x;
    if (idx >= (long long)MPATCH * DVAL) return;
    int col = (int)(idx % DVAL);
    long long r = idx / DVAL;
    int p = (int)(r % NPATCH);
    int b = (int)(r / NPATCH);
    int c = col >> 8;
    int rem = col & 255;
    int i = rem >> 4, j = rem & 15;
    int py = p / 14, px = p % 14;
    g_col[idx] = x[(((long long)b * 3 + c) * 224 + py * 16 + i) * 224 + px * 16 + j];
}

__global__ void assemble_tok_kernel(const float* __restrict__ patch,
                                    const float* __restrict__ cls,
                                    const float* __restrict__ pos)
{
    long long idx = (long long)blockIdx.x * blockDim.x + threadIdx.x;
    if (idx >= (long long)MTOK * DVAL) return;
    int d = (int)(idx % DVAL);
    long long r = idx / DVAL;
    int n = (int)(r % NTOK);
    int b = (int)(r / NTOK);
    float v;
    if (n == 0) v = cls[d];
    else        v = patch[((long long)b * NPATCH + (n - 1)) * DVAL + d];
    g_tok[idx] = v + pos[n * DVAL + d];
}

// ---------------- head ----------------
__global__ void head_kernel(const float* __restrict__ tok,
                            const float* __restrict__ fw, const float* __restrict__ fb,
                            const float* __restrict__ hw, const float* __restrict__ hb,
                            const float* __restrict__ h1w, const float* __restrict__ h1b,
                            const float* __restrict__ h2w, const float* __restrict__ h2b,
                            float* __restrict__ out)
{
    __shared__ float cbuf[DVAL];
    __shared__ float hid[MLPD];
    __shared__ float red[256];
    int b = blockIdx.x, tid = threadIdx.x;
    const float* t = tok + (long long)b * NTOK * DVAL;

    float v0 = t[tid], v1 = t[tid + 256], v2 = t[tid + 512];
    red[tid] = v0 + v1 + v2; __syncthreads();
    for (int o = 128; o > 0; o >>= 1) { if (tid < o) red[tid] += red[tid + o]; __syncthreads(); }
    float mu = red[0] * (1.0f / 768.0f); __syncthreads();
    float d0 = v0 - mu, d1 = v1 - mu, d2 = v2 - mu;
    red[tid] = d0 * d0 + d1 * d1 + d2 * d2; __syncthreads();
    for (int o = 128; o > 0; o >>= 1) { if (tid < o) red[tid] += red[tid + o]; __syncthreads(); }
    float rs = rsqrtf(red[0] * (1.0f / 768.0f) + 1e-5f); __syncthreads();
    float u0 = d0 * rs * fw[tid]       + fb[tid];
    float u1 = d1 * rs * fw[tid + 256] + fb[tid + 256];
    float u2 = d2 * rs * fw[tid + 512] + fb[tid + 512];

    red[tid] = u0 + u1 + u2; __syncthreads();
    for (int o = 128; o > 0; o >>= 1) { if (tid < o) red[tid] += red[tid + o]; __syncthreads(); }
    mu = red[0] * (1.0f / 768.0f); __syncthreads();
    d0 = u0 - mu; d1 = u1 - mu; d2 = u2 - mu;
    red[tid] = d0 * d0 + d1 * d1 + d2 * d2; __syncthreads();
    for (int o = 128; o > 0; o >>= 1) { if (tid < o) red[tid] += red[tid + o]; __syncthreads(); }
    rs = rsqrtf(red[0] * (1.0f / 768.0f) + 1e-5f); __syncthreads();
    cbuf[tid]       = d0 * rs * hw[tid]       + hb[tid];
    cbuf[tid + 256] = d1 * rs * hw[tid + 256] + hb[tid + 256];
    cbuf[tid + 512] = d2 * rs * hw[tid + 512] + hb[tid + 512];
    __syncthreads();

    for (int j = tid; j < MLPD; j += 256) {
        float sacc = h1b[j];
        for (int d = 0; d < DVAL; d++)
            sacc = fmaf(cbuf[d], h1w[(long long)d * MLPD + j], sacc);
        hid[j] = gelu_f(sacc);
    }
    __syncthreads();

    for (int c2 = 0; c2 < 2; c2++) {
        float part = 0.f;
        for (int j = tid; j < MLPD; j += 256)
            part = fmaf(hid[j], h2w[j * 2 + c2], part);
        red[tid] = part; __syncthreads();
        for (int o = 128; o > 0; o >>= 1) { if (tid < o) red[tid] += red[tid + o]; __syncthreads(); }
        if (tid == 0) out[b * 2 + c2] = red[0] + h2b[c2];
        __syncthreads();
    }
}

extern "C" void kernel_launch(void* const* d_in, const int* in_sizes, int n_in,
                              void* d_out, int out_size)
{
    const float* x         = (const float*)d_in[0];
    const float* conv_w    = (const float*)d_in[1];
    const float* conv_b    = (const float*)d_in[2];
    const float* cls_token = (const float*)d_in[3];
    const float* pos_embed = (const float*)d_in[4];
    const float* ln1_w     = (const float*)d_in[5];
    const float* ln1_b     = (const float*)d_in[6];
    const float* wq        = (const float*)d_in[7];
    const float* wk        = (const float*)d_in[8];
    const float* wv        = (const float*)d_in[9];
    const float* wo_w      = (const float*)d_in[10];
    const float* wo_b      = (const float*)d_in[11];
    const float* ln2_w     = (const float*)d_in[12];
    const float* ln2_b     = (const float*)d_in[13];
    const float* mlp1_w    = (const float*)d_in[14];
    const float* mlp1_b    = (const float*)d_in[15];
    const float* mlp2_w    = (const float*)d_in[16];
    const float* mlp2_b    = (const float*)d_in[17];
    const float* fnorm_w   = (const float*)d_in[18];
    const float* fnorm_b   = (const float*)d_in[19];
    const float* hln_w     = (const float*)d_in[20];
    const float* hln_b     = (const float*)d_in[21];
    const float* h1_w      = (const float*)d_in[22];
    const float* h1_b      = (const float*)d_in[23];
    const float* h2_w      = (const float*)d_in[24];
    const float* h2_b      = (const float*)d_in[25];

    float *tokp, *hp, *qkvp, *ctxp, *scp, *hidp, *colp;
    __half *bh, *bl;
    cudaGetSymbolAddress((void**)&tokp, g_tok);
    cudaGetSymbolAddress((void**)&hp,   g_hbuf);
    cudaGetSymbolAddress((void**)&qkvp, g_qkv);
    cudaGetSymbolAddress((void**)&ctxp, g_ctx);
    cudaGetSymbolAddress((void**)&scp,  g_scores);
    cudaGetSymbolAddress((void**)&hidp, g_hid);
    cudaGetSymbolAddress((void**)&colp, g_col);
    cudaGetSymbolAddress((void**)&bh,   g_bh);
    cudaGetSymbolAddress((void**)&bl,   g_bl);

    cudaFuncSetAttribute(hsgemm_kernel<0>, cudaFuncAttributeMaxDynamicSharedMemorySize, SMEM_HS);
    cudaFuncSetAttribute(hsgemm_kernel<2>, cudaFuncAttributeMaxDynamicSharedMemorySize, SMEM_HS);
    cudaFuncSetAttribute(hsgemm_kernel<3>, cudaFuncAttributeMaxDynamicSharedMemorySize, SMEM_HS);
    cudaFuncSetAttribute(hsgemm_kernel<5>, cudaFuncAttributeMaxDynamicSharedMemorySize, SMEM_HS);

    {
        long long tot = 3LL*SZ_ATT/4 + (long long)SZ_ATT/4 + 2LL*SZ_MLP/4 + (long long)DVAL*DVAL;
        int blocks = (int)((tot + 255) / 256);
        split_all_kernel<<<blocks, 256>>>(wq, wk, wv, wo_w, mlp1_w, mlp2_w, conv_w, bh, bl);
    }

    im2col_kernel<<<(int)(((long long)MPATCH * DVAL + 255) / 256), 256>>>(x);
    launch_hs(2, MPATCH, DVAL, DVAL, colp, DVAL, bh + OFF_WT, bl + OFF_WT, DVAL, ctxp, DVAL, conv_b);
    assemble_tok_kernel<<<(int)(((long long)MTOK * DVAL + 255) / 256), 256>>>(ctxp, cls_token, pos_embed);

    const long long DQ = (long long)DVAL * QKVN;
    const long long D2 = (long long)DVAL * DVAL;
    const long long DM = (long long)DVAL * MLPD;
    const long long SCS = (long long)NTOK * SCLD;

    for (int L = 0; L < DEPTH; L++) {
        ln_kernel<<<MTOK, 256>>>(tokp, hp, ln1_w + L * DVAL, ln1_b + L * DVAL);
        // fused QKV GEMM: [6304, 2304] (plain, no split)
        launch_hs(0, MTOK, QKVN, DVAL, hp, DVAL,
                  bh + OFF_QKV + L * DQ, bl + OFF_QKV + L * DQ, QKVN, qkvp, QKVN, nullptr);

        // scores = Q @ K^T (128x128 tiles, padded ld=208)
        {
            dim3 grid((NTOK + 127) / 128, (NTOK + 127) / 128, BVAL * HEADS);
            scores_gemm<<<grid, 256>>>(NTOK, NTOK, DKV,
                qkvp,             QKVN, (long long)NTOK * QKVN, DKV,
                qkvp + DVAL,      QKVN, (long long)NTOK * QKVN, DKV,
                scp,              SCLD, (long long)HEADS * SCS, SCS,
                HEADS);
        }
        softmax_kernel<<<(BVAL * HEADS * NTOK + 7) / 8, 256>>>(scp);
        // ctx = attn @ V (vectorized A over padded K=208)
        {
            dim3 grid(1, (NTOK + 127) / 128, BVAL * HEADS);
            ctx_gemm<<<grid, 256>>>(NTOK, DKV,
                scp,              (long long)HEADS * SCS, SCS,
                qkvp + 2 * DVAL,  QKVN, (long long)NTOK * QKVN, DKV,
                ctxp,             DVAL, (long long)NTOK * DVAL, DKV,
                HEADS);
        }
        // tok += ctx @ Wo + bo   (split-K x4, atomic combine)
        launch_hs(5, MTOK, DVAL, DVAL, ctxp, DVAL,
                  bh + OFF_WO + L * D2, bl + OFF_WO + L * D2, DVAL, tokp, DVAL,
                  wo_b + L * DVAL, 4);
        ln_kernel<<<MTOK, 256>>>(tokp, hp, ln2_w + L * DVAL, ln2_b + L * DVAL);
        // hid = gelu(h @ W1 + b1)
        launch_hs(2, MTOK, MLPD, DVAL, hp, DVAL,
                  bh + OFF_M1 + L * DM, bl + OFF_M1 + L * DM, MLPD, hidp, MLPD, mlp1_b + L * MLPD);
        // tok += hid @ W2 + b2   (split-K x4, atomic combine)
        launch_hs(5, MTOK, DVAL, MLPD, hidp, MLPD,
                  bh + OFF_M2 + L * DM, bl + OFF_M2 + L * DM, DVAL, tokp, DVAL,
                  mlp2_b + L * DVAL, 4);
    }

    head_kernel<<<BVAL, 256>>>(tokp, fnorm_w, fnorm_b, hln_w, hln_b,
                               h1_w, h1_b, h2_w, h2_b, (float*)d_out);
}

// round 16
// speedup vs baseline: 1.0180x; 1.0180x over previous
#include <cuda_runtime.h>
#include <cuda_fp16.h>
#include <math.h>
#include <stdint.h>

// ---------------- model constants ----------------
#define BVAL   32
#define DVAL   768
#define NTOK   197
#define NPATCH 196
#define HEADS  12
#define DKV    64
#define MLPD   3072
#define DEPTH  12
#define MTOK   (BVAL*NTOK)     // 6304
#define MPATCH (BVAL*NPATCH)   // 6272
#define SCLD   208             // padded scores row (13*16, 16B-aligned)
#define QKVN   (3*DVAL)        // 2304

// weight-plane offsets (in halves)
#define SZ_ATT  (DEPTH*DVAL*DVAL)
#define SZ_MLP  (DEPTH*DVAL*MLPD)
#define OFF_QKV 0
#define OFF_WO  (3*SZ_ATT)
#define OFF_M1  (4*SZ_ATT)
#define OFF_M2  (4*SZ_ATT + SZ_MLP)
#define OFF_WT  (4*SZ_ATT + 2*SZ_MLP)
#define SZ_ALL  (OFF_WT + DVAL*DVAL)

// ---------------- scratch ----------------
__device__ float g_tok[MTOK*DVAL];
__device__ float g_hbuf[MTOK*DVAL];
__device__ float g_qkv[(long long)MTOK*QKVN];
__device__ float g_ctx[MTOK*DVAL];
__device__ float g_scores[(long long)BVAL*HEADS*NTOK*SCLD];
__device__ float g_hid[(long long)MTOK*MLPD];
__device__ float g_col[(long long)MPATCH*DVAL];
__device__ __half g_bh[SZ_ALL];
__device__ __half g_bl[SZ_ALL];

__device__ __forceinline__ float gelu_f(float x) {
    return 0.5f * x * (1.0f + erff(x * 0.70710678118654752440f));
}

__device__ __forceinline__ void split2(float x, __half& h, __half& l) {
    h = __float2half_rn(x);
    l = __float2half_rn(x - __half2float(h));
}

__device__ __forceinline__ uint32_t smem_u32(const void* p) {
    return (uint32_t)__cvta_generic_to_shared(p);
}

__device__ __forceinline__ void cp16(uint32_t dst, const void* src) {
    asm volatile("cp.async.cg.shared.global [%0], [%1], 16;" :: "r"(dst), "l"(src));
}
#define CP_COMMIT() asm volatile("cp.async.commit_group;")
#define CP_WAIT0()  asm volatile("cp.async.wait_group 0;")

__device__ __forceinline__ void ldsm_x4(uint32_t* r, uint32_t addr) {
    asm volatile("ldmatrix.sync.aligned.m8n8.x4.shared.b16 {%0,%1,%2,%3}, [%4];"
                 : "=r"(r[0]), "=r"(r[1]), "=r"(r[2]), "=r"(r[3]) : "r"(addr));
}
__device__ __forceinline__ void ldsm_x4_t(uint32_t* r, uint32_t addr) {
    asm volatile("ldmatrix.sync.aligned.m8n8.x4.trans.shared.b16 {%0,%1,%2,%3}, [%4];"
                 : "=r"(r[0]), "=r"(r[1]), "=r"(r[2]), "=r"(r[3]) : "r"(addr));
}
__device__ __forceinline__ void mma16816(float* c, const uint32_t* a, const uint32_t* b) {
    asm volatile("mma.sync.aligned.m16n8k16.row.col.f32.f16.f16.f32 "
                 "{%0,%1,%2,%3},{%4,%5,%6,%7},{%8,%9},{%0,%1,%2,%3};"
                 : "+f"(c[0]), "+f"(c[1]), "+f"(c[2]), "+f"(c[3])
                 : "r"(a[0]), "r"(a[1]), "r"(a[2]), "r"(a[3]), "r"(b[0]), "r"(b[1]));
}

// =========================================================================
// fp16-split (3-term) tensor-core GEMM: 128x128 tile, 256 thr, occ 2,
// KC=32. A fp32 via LDG + in-kernel split (L1 reuse), B pre-split cp.async
// (2-stage). Split-K aware. EPI: 0=store; 2=gelu(acc+bias); 3=C+=; 5=atomicAdd
// =========================================================================
#define ASTR 40
#define BSTR 136
#define A_PL (128*ASTR)
#define B_PL (32*BSTR)
#define SMEM_HS ((4*A_PL + 4*B_PL) * 2)   // 75776 bytes

template<int EPI>
__global__ __launch_bounds__(256, 2)
void hsgemm_kernel(int M, int N, int K,
                   const float* __restrict__ A, int lda,
                   const __half* __restrict__ Bh, const __half* __restrict__ Bl, int ldb,
                   float* __restrict__ C, int ldc,
                   const float* __restrict__ bias)
{
    extern __shared__ __half sm[];
    __half* Ahs = sm;
    __half* Als = sm + 2 * A_PL;
    __half* Bhs = sm + 4 * A_PL;
    __half* Bls = sm + 4 * A_PL + 2 * B_PL;

    const int tid = threadIdx.x;
    const int lane = tid & 31, wid = tid >> 5;
    const int warpM = wid >> 2, warpN = wid & 3;
    const int quad = lane & 3, gid = lane >> 2;
    const int row0 = blockIdx.y * 128, col0 = blockIdx.x * 128;

    const int kLen = K / gridDim.z;
    const int zoff = blockIdx.z * kLen;
    A  += zoff;
    Bh += (size_t)zoff * ldb;
    Bl += (size_t)zoff * ldb;

    float acc[4][4][4];
    #pragma unroll
    for (int i = 0; i < 4; i++)
        #pragma unroll
        for (int j = 0; j < 4; j++)
            #pragma unroll
            for (int r = 0; r < 4; r++) acc[i][j][r] = 0.f;

    int aR[4], aC[4];
    #pragma unroll
    for (int i = 0; i < 4; i++) {
        int e = tid + i * 256;
        aR[i] = e >> 3;  aC[i] = (e & 7) * 4;
    }
    int bRow[2], bCg[2];
    #pragma unroll
    for (int i = 0; i < 2; i++) {
        int c = tid + i * 256;
        bRow[i] = c >> 4; bCg[i] = (c & 15) * 8;
    }

    const int nk = kLen / 32;
    float4 va[4];

    #pragma unroll
    for (int i = 0; i < 2; i++) {
        uint32_t db = (uint32_t)((bRow[i] * BSTR + bCg[i]) * 2);
        cp16(smem_u32(Bhs) + db, Bh + (size_t)bRow[i] * ldb + col0 + bCg[i]);
        cp16(smem_u32(Bls) + db, Bl + (size_t)bRow[i] * ldb + col0 + bCg[i]);
    }
    CP_COMMIT();
    #pragma unroll
    for (int i = 0; i < 4; i++) {
        int gm = row0 + aR[i];
        va[i] = (gm < M) ? *(const float4*)(A + (size_t)gm * lda + aC[i])
                         : make_float4(0.f, 0.f, 0.f, 0.f);
    }
    #pragma unroll
    for (int i = 0; i < 4; i++) {
        __half h0,h1,h2,h3,l0,l1,l2,l3;
        split2(va[i].x,h0,l0); split2(va[i].y,h1,l1);
        split2(va[i].z,h2,l2); split2(va[i].w,h3,l3);
        __half2* ph = (__half2*)&Ahs[aR[i]*ASTR + aC[i]];
        ph[0] = __halves2half2(h0,h1); ph[1] = __halves2half2(h2,h3);
        __half2* pl = (__half2*)&Als[aR[i]*ASTR + aC[i]];
        pl[0] = __halves2half2(l0,l1); pl[1] = __halves2half2(l2,l3);
    }
    CP_WAIT0();
    __syncthreads();

    for (int kt = 0; kt < nk; kt++) {
        const int cur = kt & 1;
        const bool more = (kt + 1 < nk);
        if (more) {
            const int k0 = (kt + 1) * 32;
            const int nxt = cur ^ 1;
            #pragma unroll
            for (int i = 0; i < 2; i++) {
                uint32_t db = (uint32_t)((nxt * B_PL + bRow[i] * BSTR + bCg[i]) * 2);
                cp16(smem_u32(Bhs) + db, Bh + (size_t)(k0 + bRow[i]) * ldb + col0 + bCg[i]);
                cp16(smem_u32(Bls) + db, Bl + (size_t)(k0 + bRow[i]) * ldb + col0 + bCg[i]);
            }
            CP_COMMIT();
            #pragma unroll
            for (int i = 0; i < 4; i++) {
                int gm = row0 + aR[i];
                va[i] = (gm < M) ? *(const float4*)(A + (size_t)gm * lda + k0 + aC[i])
                                 : make_float4(0.f, 0.f, 0.f, 0.f);
            }
        }

        #pragma unroll
        for (int ks = 0; ks < 32; ks += 16) {
            uint32_t ah[4][4], al[4][4], bh[4][2], bl[4][2];
            const uint32_t aoff = (uint32_t)((cur * A_PL + (lane & 15) * ASTR + ks + (lane >> 4) * 8) * 2);
            const uint32_t ah_base = smem_u32(Ahs) + aoff;
            const uint32_t al_base = smem_u32(Als) + aoff;
            #pragma unroll
            for (int mi = 0; mi < 4; mi++) {
                uint32_t o = (uint32_t)((warpM * 64 + mi * 16) * ASTR * 2);
                ldsm_x4(ah[mi], ah_base + o);
                ldsm_x4(al[mi], al_base + o);
            }
            const uint32_t boff = (uint32_t)((cur * B_PL + (ks + (lane & 15)) * BSTR + (lane >> 4) * 8) * 2);
            const uint32_t bh_base = smem_u32(Bhs) + boff;
            const uint32_t bl_base = smem_u32(Bls) + boff;
            #pragma unroll
            for (int np = 0; np < 2; np++) {
                uint32_t o = (uint32_t)((warpN * 32 + np * 16) * 2);
                uint32_t r[4];
                ldsm_x4_t(r, bh_base + o);
                bh[np*2][0] = r[0]; bh[np*2][1] = r[1];
                bh[np*2+1][0] = r[2]; bh[np*2+1][1] = r[3];
                ldsm_x4_t(r, bl_base + o);
                bl[np*2][0] = r[0]; bl[np*2][1] = r[1];
                bl[np*2+1][0] = r[2]; bl[np*2+1][1] = r[3];
            }
            #pragma unroll
            for (int mi = 0; mi < 4; mi++)
                #pragma unroll
                for (int ni = 0; ni < 4; ni++) {
                    mma16816(acc[mi][ni], ah[mi], bh[ni]);
                    mma16816(acc[mi][ni], ah[mi], bl[ni]);
                    mma16816(acc[mi][ni], al[mi], bh[ni]);
                }
        }

        if (more) {
            const int nxt = cur ^ 1;
            #pragma unroll
            for (int i = 0; i < 4; i++) {
                __half h0,h1,h2,h3,l0,l1,l2,l3;
                split2(va[i].x,h0,l0); split2(va[i].y,h1,l1);
                split2(va[i].z,h2,l2); split2(va[i].w,h3,l3);
                __half2* ph = (__half2*)&Ahs[nxt*A_PL + aR[i]*ASTR + aC[i]];
                ph[0] = __halves2half2(h0,h1); ph[1] = __halves2half2(h2,h3);
                __half2* pl = (__half2*)&Als[nxt*A_PL + aR[i]*ASTR + aC[i]];
                pl[0] = __halves2half2(l0,l1); pl[1] = __halves2half2(l2,l3);
            }
            CP_WAIT0();
            __syncthreads();
        }
    }

    const bool addBias = (EPI == 2 || EPI == 3) || (EPI == 5 && blockIdx.z == 0 && bias != nullptr);
    #pragma unroll
    for (int mi = 0; mi < 4; mi++) {
        int rr[2];
        rr[0] = row0 + warpM * 64 + mi * 16 + gid;
        rr[1] = rr[0] + 8;
        #pragma unroll
        for (int ni = 0; ni < 4; ni++) {
            int c = col0 + warpN * 32 + ni * 8 + 2 * quad;
            float b0 = 0.f, b1 = 0.f;
            if (EPI >= 2 && addBias) { b0 = bias[c]; b1 = bias[c + 1]; }
            #pragma unroll
            for (int h = 0; h < 2; h++) {
                if (rr[h] >= M) continue;
                float x0 = acc[mi][ni][2*h]     + b0;
                float x1 = acc[mi][ni][2*h + 1] + b1;
                if (EPI == 2) { x0 = gelu_f(x0); x1 = gelu_f(x1); }
                size_t idx = (size_t)rr[h] * ldc + c;
                if (EPI == 3)      { C[idx] += x0; C[idx + 1] += x1; }
                else if (EPI == 5) { atomicAdd(&C[idx], x0); atomicAdd(&C[idx + 1], x1); }
                else               { C[idx] = x0;  C[idx + 1] = x1; }
            }
        }
    }
}

static void launch_hs(int epi, int M, int N, int K,
                      const float* A, int lda,
                      const __half* Bh, const __half* Bl, int ldb,
                      float* C, int ldc, const float* bias, int splits = 1)
{
    dim3 grid(N / 128, (M + 127) / 128, splits), blk(256);
    if      (epi == 0) hsgemm_kernel<0><<<grid, blk, SMEM_HS>>>(M, N, K, A, lda, Bh, Bl, ldb, C, ldc, bias);
    else if (epi == 2) hsgemm_kernel<2><<<grid, blk, SMEM_HS>>>(M, N, K, A, lda, Bh, Bl, ldb, C, ldc, bias);
    else if (epi == 3) hsgemm_kernel<3><<<grid, blk, SMEM_HS>>>(M, N, K, A, lda, Bh, Bl, ldb, C, ldc, bias);
    else               hsgemm_kernel<5><<<grid, blk, SMEM_HS>>>(M, N, K, A, lda, Bh, Bl, ldb, C, ldc, bias);
}

// =========================================================================
// scores GEMM: QK^T, tile 128(M) x 128(N), 8 warps 2x4 (64x32 warp tiles),
// both operands via float4 staging + in-kernel split. K=64 (4 k-iters).
// =========================================================================
#define ASTR3 24
#define BSTR3 136

__global__ __launch_bounds__(256)
void scores_gemm(int M, int N, int K,
                 const float* __restrict__ A, int lda, long long sA0, long long sA1,
                 const float* __restrict__ B, int ldb, long long sB0, long long sB1,
                 float* __restrict__ C, int ldc, long long sC0, long long sC1,
                 int hdiv)
{
    __shared__ __align__(16) __half As[2][128 * ASTR3];
    __shared__ __align__(16) __half Bs[2][16 * BSTR3];

    const int z = blockIdx.z;
    const int zb = z / hdiv, zh = z - zb * hdiv;
    A += zb * sA0 + zh * sA1;
    B += zb * sB0 + zh * sB1;
    C += zb * sC0 + zh * sC1;

    const int tid = threadIdx.x;
    const int lane = tid & 31, wid = tid >> 5;
    const int warpM = wid >> 2, warpN = wid & 3;
    const int quad = lane & 3, gid = lane >> 2;
    const int row0 = blockIdx.y * 128, col0 = blockIdx.x * 128;

    float acc[4][4][4];
    #pragma unroll
    for (int i = 0; i < 4; i++)
        #pragma unroll
        for (int j = 0; j < 4; j++)
            #pragma unroll
            for (int r = 0; r < 4; r++) acc[i][j][r] = 0.f;

    const int nk = K / 16;   // 4

    for (int kt = 0; kt < nk; kt++) {
        const int k0 = kt * 16;
        #pragma unroll
        for (int i = 0; i < 2; i++) {
            int e = tid + i * 256;
            int ar = e >> 2, ac = (e & 3) * 4;
            int gm = row0 + ar;
            float4 v = (gm < M) ? *(const float4*)(A + (size_t)gm * lda + k0 + ac)
                                : make_float4(0.f, 0.f, 0.f, 0.f);
            __half h0,h1,h2,h3,l0,l1,l2,l3;
            split2(v.x,h0,l0); split2(v.y,h1,l1);
            split2(v.z,h2,l2); split2(v.w,h3,l3);
            __half2* ph = (__half2*)&As[0][ar * ASTR3 + ac];
            ph[0] = __halves2half2(h0,h1); ph[1] = __halves2half2(h2,h3);
            __half2* pl = (__half2*)&As[1][ar * ASTR3 + ac];
            pl[0] = __halves2half2(l0,l1); pl[1] = __halves2half2(l2,l3);
        }
        #pragma unroll
        for (int i = 0; i < 2; i++) {
            int e = tid + i * 256;
            int nr = e >> 2, kc = (e & 3) * 4;
            int gn = col0 + nr;
            float4 v = (gn < N) ? *(const float4*)(B + (size_t)gn * ldb + k0 + kc)
                                : make_float4(0.f, 0.f, 0.f, 0.f);
            float vv[4] = {v.x, v.y, v.z, v.w};
            #pragma unroll
            for (int j = 0; j < 4; j++) {
                __half h, l; split2(vv[j], h, l);
                Bs[0][(kc + j) * BSTR3 + nr] = h;
                Bs[1][(kc + j) * BSTR3 + nr] = l;
            }
        }
        __syncthreads();

        {
            uint32_t ah[4][4], al[4][4], bh[4][2], bl[4][2];
            const uint32_t aoff = (uint32_t)(((lane & 15) * ASTR3 + (lane >> 4) * 8) * 2);
            const uint32_t ah_base = smem_u32(&As[0][0]) + aoff;
            const uint32_t al_base = smem_u32(&As[1][0]) + aoff;
            #pragma unroll
            for (int mi = 0; mi < 4; mi++) {
                uint32_t o = (uint32_t)((warpM * 64 + mi * 16) * ASTR3 * 2);
                ldsm_x4(ah[mi], ah_base + o);
                ldsm_x4(al[mi], al_base + o);
            }
            const uint32_t boff = (uint32_t)(((lane & 15) * BSTR3 + (lane >> 4) * 8) * 2);
            const uint32_t bh_base = smem_u32(&Bs[0][0]) + boff;
            const uint32_t bl_base = smem_u32(&Bs[1][0]) + boff;
            #pragma unroll
            for (int np = 0; np < 2; np++) {
                uint32_t o = (uint32_t)((warpN * 32 + np * 16) * 2);
                uint32_t r[4];
                ldsm_x4_t(r, bh_base + o);
                bh[np*2][0] = r[0]; bh[np*2][1] = r[1];
                bh[np*2+1][0] = r[2]; bh[np*2+1][1] = r[3];
                ldsm_x4_t(r, bl_base + o);
                bl[np*2][0] = r[0]; bl[np*2][1] = r[1];
                bl[np*2+1][0] = r[2]; bl[np*2+1][1] = r[3];
            }
            #pragma unroll
            for (int mi = 0; mi < 4; mi++)
                #pragma unroll
                for (int ni = 0; ni < 4; ni++) {
                    mma16816(acc[mi][ni], ah[mi], bh[ni]);
                    mma16816(acc[mi][ni], ah[mi], bl[ni]);
                    mma16816(acc[mi][ni], al[mi], bh[ni]);
                }
        }
        __syncthreads();
    }

    #pragma unroll
    for (int mi = 0; mi < 4; mi++) {
        int rr[2];
        rr[0] = row0 + warpM * 64 + mi * 16 + gid;
        rr[1] = rr[0] + 8;
        #pragma unroll
        for (int ni = 0; ni < 4; ni++) {
            int c = col0 + warpN * 32 + ni * 8 + 2 * quad;
            #pragma unroll
            for (int h = 0; h < 2; h++) {
                if (rr[h] >= M) continue;
                size_t idx = (size_t)rr[h] * ldc + c;
                if (c < N)     C[idx]     = acc[mi][ni][2*h];
                if (c + 1 < N) C[idx + 1] = acc[mi][ni][2*h + 1];
            }
        }
    }
}

// =========================================================================
// ctx GEMM (attn @ V): tile 128(M) x 64(N). A (scores, ld=SCLD, zero-padded
// cols) staged via float4; V staged scalar with real kv bound (NTOK).
// =========================================================================
#define ASTR2 24
#define BSTR2 72

__global__ __launch_bounds__(256)
void ctx_gemm(int M, int N,
              const float* __restrict__ A, long long sA0, long long sA1,
              const float* __restrict__ B, int ldb, long long sB0, long long sB1,
              float* __restrict__ C, int ldc, long long sC0, long long sC1,
              int hdiv)
{
    __shared__ __align__(16) __half As[2][128 * ASTR2];
    __shared__ __align__(16) __half Bs[2][16 * BSTR2];

    const int z = blockIdx.z;
    const int zb = z / hdiv, zh = z - zb * hdiv;
    A += zb * sA0 + zh * sA1;
    B += zb * sB0 + zh * sB1;
    C += zb * sC0 + zh * sC1;

    const int tid = threadIdx.x;
    const int lane = tid & 31, wid = tid >> 5;
    const int warpM = wid >> 1, warpN = wid & 1;
    const int quad = lane & 3, gid = lane >> 2;
    const int row0 = blockIdx.y * 128, col0 = blockIdx.x * 64;

    float acc[2][4][4];
    #pragma unroll
    for (int i = 0; i < 2; i++)
        #pragma unroll
        for (int j = 0; j < 4; j++)
            #pragma unroll
            for (int r = 0; r < 4; r++) acc[i][j][r] = 0.f;

    const int nk = SCLD / 16;   // 13

    for (int kt = 0; kt < nk; kt++) {
        const int k0 = kt * 16;
        #pragma unroll
        for (int i = 0; i < 2; i++) {
            int e = tid + i * 256;
            int ar = e >> 2, ac = (e & 3) * 4;
            int gm = row0 + ar;
            float4 v = (gm < M) ? *(const float4*)(A + (size_t)gm * SCLD + k0 + ac)
                                : make_float4(0.f, 0.f, 0.f, 0.f);
            __half h0,h1,h2,h3,l0,l1,l2,l3;
            split2(v.x,h0,l0); split2(v.y,h1,l1);
            split2(v.z,h2,l2); split2(v.w,h3,l3);
            __half2* ph = (__half2*)&As[0][ar * ASTR2 + ac];
            ph[0] = __halves2half2(h0,h1); ph[1] = __halves2half2(h2,h3);
            __half2* pl = (__half2*)&As[1][ar * ASTR2 + ac];
            pl[0] = __halves2half2(l0,l1); pl[1] = __halves2half2(l2,l3);
        }
        {
            int kl = tid >> 4, nc = (tid & 15) * 4;
            int gk = k0 + kl;
            #pragma unroll
            for (int j = 0; j < 4; j++) {
                int gn = col0 + nc + j;
                float v = (gk < NTOK && gn < N) ? B[(size_t)gk * ldb + gn] : 0.f;
                __half h, l; split2(v, h, l);
                Bs[0][kl * BSTR2 + nc + j] = h;
                Bs[1][kl * BSTR2 + nc + j] = l;
            }
        }
        __syncthreads();

        {
            uint32_t ah[2][4], al[2][4], bh[4][2], bl[4][2];
            const uint32_t aoff = (uint32_t)(((lane & 15) * ASTR2 + (lane >> 4) * 8) * 2);
            const uint32_t ah_base = smem_u32(&As[0][0]) + aoff;
            const uint32_t al_base = smem_u32(&As[1][0]) + aoff;
            #pragma unroll
            for (int mi = 0; mi < 2; mi++) {
                uint32_t o = (uint32_t)((warpM * 32 + mi * 16) * ASTR2 * 2);
                ldsm_x4(ah[mi], ah_base + o);
                ldsm_x4(al[mi], al_base + o);
            }
            const uint32_t boff = (uint32_t)(((lane & 15) * BSTR2 + (lane >> 4) * 8) * 2);
            const uint32_t bh_base = smem_u32(&Bs[0][0]) + boff;
            const uint32_t bl_base = smem_u32(&Bs[1][0]) + boff;
            #pragma unroll
            for (int np = 0; np < 2; np++) {
                uint32_t o = (uint32_t)((warpN * 32 + np * 16) * 2);
                uint32_t r[4];
                ldsm_x4_t(r, bh_base + o);
                bh[np*2][0] = r[0]; bh[np*2][1] = r[1];
                bh[np*2+1][0] = r[2]; bh[np*2+1][1] = r[3];
                ldsm_x4_t(r, bl_base + o);
                bl[np*2][0] = r[0]; bl[np*2][1] = r[1];
                bl[np*2+1][0] = r[2]; bl[np*2+1][1] = r[3];
            }
            #pragma unroll
            for (int mi = 0; mi < 2; mi++)
                #pragma unroll
                for (int ni = 0; ni < 4; ni++) {
                    mma16816(acc[mi][ni], ah[mi], bh[ni]);
                    mma16816(acc[mi][ni], ah[mi], bl[ni]);
                    mma16816(acc[mi][ni], al[mi], bh[ni]);
                }
        }
        __syncthreads();
    }

    #pragma unroll
    for (int mi = 0; mi < 2; mi++) {
        int rr[2];
        rr[0] = row0 + warpM * 32 + mi * 16 + gid;
        rr[1] = rr[0] + 8;
        #pragma unroll
        for (int ni = 0; ni < 4; ni++) {
            int c = col0 + warpN * 32 + ni * 8 + 2 * quad;
            #pragma unroll
            for (int h = 0; h < 2; h++) {
                if (rr[h] >= M) continue;
                size_t idx = (size_t)rr[h] * ldc + c;
                if (c < N)     C[idx]     = acc[mi][ni][2*h];
                if (c + 1 < N) C[idx + 1] = acc[mi][ni][2*h + 1];
            }
        }
    }
}

// =========================================================================
// mega weight split (QKV packed + wo + mlp1 + mlp2 + convT)
// =========================================================================
__global__ void split_all_kernel(const float* __restrict__ wq, const float* __restrict__ wk,
                                 const float* __restrict__ wv, const float* __restrict__ wo,
                                 const float* __restrict__ m1, const float* __restrict__ m2,
                                 const float* __restrict__ cw,
                                 __half* __restrict__ bh, __half* __restrict__ bl)
{
    const long long QKV4 = 3LL * SZ_ATT / 4;
    const long long WO4  = (long long)SZ_ATT / 4;
    const long long M4   = (long long)SZ_MLP / 4;
    const long long TOT4 = QKV4 + WO4 + 2 * M4;

    long long i = (long long)blockIdx.x * 256 + threadIdx.x;

    if (i < QKV4) {
        int w = (int)(i / (SZ_ATT / 4));
        long long j = i - (long long)w * (SZ_ATT / 4);
        const float* src = (w == 0) ? wq : (w == 1) ? wk : wv;
        float4 v = ((const float4*)src)[j];
        long long s = 4 * j;
        int L = (int)(s / ((long long)DVAL * DVAL));
        int r = (int)(s - (long long)L * DVAL * DVAL);
        int k = r / DVAL, n = r - k * DVAL;
        long long d = OFF_QKV + (long long)L * DVAL * QKVN + (long long)k * QKVN + w * DVAL + n;
        __half h0,h1,h2,h3,l0,l1,l2,l3;
        split2(v.x,h0,l0); split2(v.y,h1,l1); split2(v.z,h2,l2); split2(v.w,h3,l3);
        __half2* ph = (__half2*)(bh + d);
        ph[0] = __halves2half2(h0,h1); ph[1] = __halves2half2(h2,h3);
        __half2* pl = (__half2*)(bl + d);
        pl[0] = __halves2half2(l0,l1); pl[1] = __halves2half2(l2,l3);
        return;
    }
    if (i < TOT4) {
        long long i2 = i - QKV4;
        const float* src; long long off, j;
        if (i2 < WO4)            { src = wo; off = OFF_WO; j = i2; }
        else if (i2 < WO4 + M4)  { src = m1; off = OFF_M1; j = i2 - WO4; }
        else                     { src = m2; off = OFF_M2; j = i2 - WO4 - M4; }
        float4 v = ((const float4*)src)[j];
        long long d = off + 4 * j;
        __half h0,h1,h2,h3,l0,l1,l2,l3;
        split2(v.x,h0,l0); split2(v.y,h1,l1); split2(v.z,h2,l2); split2(v.w,h3,l3);
        __half2* ph = (__half2*)(bh + d);
        ph[0] = __halves2half2(h0,h1); ph[1] = __halves2half2(h2,h3);
        __half2* pl = (__half2*)(bl + d);
        pl[0] = __halves2half2(l0,l1); pl[1] = __halves2half2(l2,l3);
        return;
    }
    long long idx = i - TOT4;
    if (idx < (long long)DVAL * DVAL) {
        int k = (int)(idx / DVAL), n = (int)(idx % DVAL);
        float x = cw[(long long)n * DVAL + k];
        __half h, l; split2(x, h, l);
        bh[OFF_WT + idx] = h;
        bl[OFF_WT + idx] = l;
    }
}

// ---------------- LayerNorm (warp-shuffle reductions) ----------------
__global__ void ln_kernel(const float* __restrict__ in, float* __restrict__ out,
                          const float* __restrict__ w, const float* __restrict__ b)
{
    __shared__ float red[8];
    int row = blockIdx.x;
    int tid = threadIdx.x;
    int lane = tid & 31, wd = tid >> 5;
    const float* x = in + (long long)row * DVAL;

    float v0 = x[tid], v1 = x[tid + 256], v2 = x[tid + 512];
    float s = v0 + v1 + v2;
    #pragma unroll
    for (int o = 16; o > 0; o >>= 1) s += __shfl_xor_sync(0xffffffffu, s, o);
    if (lane == 0) red[wd] = s;
    __syncthreads();
    float mu = (red[0] + red[1] + red[2] + red[3] + red[4] + red[5] + red[6] + red[7])
               * (1.0f / 768.0f);

    float d0 = v0 - mu, d1 = v1 - mu, d2 = v2 - mu;
    float s2 = d0 * d0 + d1 * d1 + d2 * d2;
    #pragma unroll
    for (int o = 16; o > 0; o >>= 1) s2 += __shfl_xor_sync(0xffffffffu, s2, o);
    __syncthreads();
    if (lane == 0) red[wd] = s2;
    __syncthreads();
    float rs = rsqrtf((red[0] + red[1] + red[2] + red[3] + red[4] + red[5] + red[6] + red[7])
                      * (1.0f / 768.0f) + 1e-5f);

    float* y = out + (long long)row * DVAL;
    y[tid]       = d0 * rs * w[tid]       + b[tid];
    y[tid + 256] = d1 * rs * w[tid + 256] + b[tid + 256];
    y[tid + 512] = d2 * rs * w[tid + 512] + b[tid + 512];
}

// ---------------- softmax (rows of SCLD; zero pad cols 197..207) ----------------
__global__ void softmax_kernel(float* __restrict__ s)
{
    int row = blockIdx.x * 8 + (threadIdx.x >> 5);
    if (row >= BVAL * HEADS * NTOK) return;
    int lane = threadIdx.x & 31;
    float* p = s + (long long)row * SCLD;
    const float scale = 0.125f;

    float vals[7];
    float mx = -1e30f;
    #pragma unroll
    for (int i = 0; i < 7; i++) {
        int c = lane + i * 32;
        float v = (c < NTOK) ? p[c] * scale : -1e30f;
        vals[i] = v;
        mx = fmaxf(mx, v);
    }
    #pragma unroll
    for (int o = 16; o > 0; o >>= 1) mx = fmaxf(mx, __shfl_xor_sync(0xffffffffu, mx, o));

    float sum = 0.f;
    #pragma unroll
    for (int i = 0; i < 7; i++) {
        int c = lane + i * 32;
        float e = (c < NTOK) ? __expf(vals[i] - mx) : 0.f;
        vals[i] = e;
        sum += e;
    }
    #pragma unroll
    for (int o = 16; o > 0; o >>= 1) sum += __shfl_xor_sync(0xffffffffu, sum, o);
    float inv = 1.0f / sum;

    #pragma unroll
    for (int i = 0; i < 7; i++) {
        int c = lane + i * 32;
        if (c < NTOK)      p[c] = vals[i] * inv;
        else if (c < SCLD) p[c] = 0.f;
    }
}

// ---------------- patch-embed helpers ----------------
__global__ void im2col_kernel(const float* __restrict__ x)
{
    long long idx = (long long)blockIdx.x * blockDim.x + threadIdx.x;
    if (idx >= (long long)MPATCH * DVAL) return;
    int col = (int)(idx % DVAL);
    long long r = idx / DVAL;
    int p = (int)(r % NPATCH);
    int b = (int)(r / NPATCH);
    int c = col >> 8;
    int rem = col & 255;
    int i = rem >> 4, j = rem & 15;
    int py = p / 14, px = p % 14;
    g_col[idx] = x[(((long long)b * 3 + c) * 224 + py * 16 + i) * 224 + px * 16 + j];
}

__global__ void assemble_tok_kernel(const float* __restrict__ patch,
                                    const float* __restrict__ cls,
                                    const float* __restrict__ pos)
{
    long long idx = (long long)blockIdx.x * blockDim.x + threadIdx.x;
    if (idx >= (long long)MTOK * DVAL) return;
    int d = (int)(idx % DVAL);
    long long r = idx / DVAL;
    int n = (int)(r % NTOK);
    int b = (int)(r / NTOK);
    float v;
    if (n == 0) v = cls[d];
    else        v = patch[((long long)b * NPATCH + (n - 1)) * DVAL + d];
    g_tok[idx] = v + pos[n * DVAL + d];
}

// ---------------- head ----------------
__global__ void head_kernel(const float* __restrict__ tok,
                            const float* __restrict__ fw, const float* __restrict__ fb,
                            const float* __restrict__ hw, const float* __restrict__ hb,
                            const float* __restrict__ h1w, const float* __restrict__ h1b,
                            const float* __restrict__ h2w, const float* __restrict__ h2b,
                            float* __restrict__ out)
{
    __shared__ float cbuf[DVAL];
    __shared__ float hid[MLPD];
    __shared__ float red[256];
    int b = blockIdx.x, tid = threadIdx.x;
    const float* t = tok + (long long)b * NTOK * DVAL;

    float v0 = t[tid], v1 = t[tid + 256], v2 = t[tid + 512];
    red[tid] = v0 + v1 + v2; __syncthreads();
    for (int o = 128; o > 0; o >>= 1) { if (tid < o) red[tid] += red[tid + o]; __syncthreads(); }
    float mu = red[0] * (1.0f / 768.0f); __syncthreads();
    float d0 = v0 - mu, d1 = v1 - mu, d2 = v2 - mu;
    red[tid] = d0 * d0 + d1 * d1 + d2 * d2; __syncthreads();
    for (int o = 128; o > 0; o >>= 1) { if (tid < o) red[tid] += red[tid + o]; __syncthreads(); }
    float rs = rsqrtf(red[0] * (1.0f / 768.0f) + 1e-5f); __syncthreads();
    float u0 = d0 * rs * fw[tid]       + fb[tid];
    float u1 = d1 * rs * fw[tid + 256] + fb[tid + 256];
    float u2 = d2 * rs * fw[tid + 512] + fb[tid + 512];

    red[tid] = u0 + u1 + u2; __syncthreads();
    for (int o = 128; o > 0; o >>= 1) { if (tid < o) red[tid] += red[tid + o]; __syncthreads(); }
    mu = red[0] * (1.0f / 768.0f); __syncthreads();
    d0 = u0 - mu; d1 = u1 - mu; d2 = u2 - mu;
    red[tid] = d0 * d0 + d1 * d1 + d2 * d2; __syncthreads();
    for (int o = 128; o > 0; o >>= 1) { if (tid < o) red[tid] += red[tid + o]; __syncthreads(); }
    rs = rsqrtf(red[0] * (1.0f / 768.0f) + 1e-5f); __syncthreads();
    cbuf[tid]       = d0 * rs * hw[tid]       + hb[tid];
    cbuf[tid + 256] = d1 * rs * hw[tid + 256] + hb[tid + 256];
    cbuf[tid + 512] = d2 * rs * hw[tid + 512] + hb[tid + 512];
    __syncthreads();

    for (int j = tid; j < MLPD; j += 256) {
        float sacc = h1b[j];
        for (int d = 0; d < DVAL; d++)
            sacc = fmaf(cbuf[d], h1w[(long long)d * MLPD + j], sacc);
        hid[j] = gelu_f(sacc);
    }
    __syncthreads();

    for (int c2 = 0; c2 < 2; c2++) {
        float part = 0.f;
        for (int j = tid; j < MLPD; j += 256)
            part = fmaf(hid[j], h2w[j * 2 + c2], part);
        red[tid] = part; __syncthreads();
        for (int o = 128; o > 0; o >>= 1) { if (tid < o) red[tid] += red[tid + o]; __syncthreads(); }
        if (tid == 0) out[b * 2 + c2] = red[0] + h2b[c2];
        __syncthreads();
    }
}

extern "C" void kernel_launch(void* const* d_in, const int* in_sizes, int n_in,
                              void* d_out, int out_size)
{
    const float* x         = (const float*)d_in[0];
    const float* conv_w    = (const float*)d_in[1];
    const float* conv_b    = (const float*)d_in[2];
    const float* cls_token = (const float*)d_in[3];
    const float* pos_embed = (const float*)d_in[4];
    const float* ln1_w     = (const float*)d_in[5];
    const float* ln1_b     = (const float*)d_in[6];
    const float* wq        = (const float*)d_in[7];
    const float* wk        = (const float*)d_in[8];
    const float* wv        = (const float*)d_in[9];
    const float* wo_w      = (const float*)d_in[10];
    const float* wo_b      = (const float*)d_in[11];
    const float* ln2_w     = (const float*)d_in[12];
    const float* ln2_b     = (const float*)d_in[13];
    const float* mlp1_w    = (const float*)d_in[14];
    const float* mlp1_b    = (const float*)d_in[15];
    const float* mlp2_w    = (const float*)d_in[16];
    const float* mlp2_b    = (const float*)d_in[17];
    const float* fnorm_w   = (const float*)d_in[18];
    const float* fnorm_b   = (const float*)d_in[19];
    const float* hln_w     = (const float*)d_in[20];
    const float* hln_b     = (const float*)d_in[21];
    const float* h1_w      = (const float*)d_in[22];
    const float* h1_b      = (const float*)d_in[23];
    const float* h2_w      = (const float*)d_in[24];
    const float* h2_b      = (const float*)d_in[25];

    float *tokp, *hp, *qkvp, *ctxp, *scp, *hidp, *colp;
    __half *bh, *bl;
    cudaGetSymbolAddress((void**)&tokp, g_tok);
    cudaGetSymbolAddress((void**)&hp,   g_hbuf);
    cudaGetSymbolAddress((void**)&qkvp, g_qkv);
    cudaGetSymbolAddress((void**)&ctxp, g_ctx);
    cudaGetSymbolAddress((void**)&scp,  g_scores);
    cudaGetSymbolAddress((void**)&hidp, g_hid);
    cudaGetSymbolAddress((void**)&colp, g_col);
    cudaGetSymbolAddress((void**)&bh,   g_bh);
    cudaGetSymbolAddress((void**)&bl,   g_bl);

    cudaFuncSetAttribute(hsgemm_kernel<0>, cudaFuncAttributeMaxDynamicSharedMemorySize, SMEM_HS);
    cudaFuncSetAttribute(hsgemm_kernel<2>, cudaFuncAttributeMaxDynamicSharedMemorySize, SMEM_HS);
    cudaFuncSetAttribute(hsgemm_kernel<3>, cudaFuncAttributeMaxDynamicSharedMemorySize, SMEM_HS);
    cudaFuncSetAttribute(hsgemm_kernel<5>, cudaFuncAttributeMaxDynamicSharedMemorySize, SMEM_HS);

    {
        long long tot = 3LL*SZ_ATT/4 + (long long)SZ_ATT/4 + 2LL*SZ_MLP/4 + (long long)DVAL*DVAL;
        int blocks = (int)((tot + 255) / 256);
        split_all_kernel<<<blocks, 256>>>(wq, wk, wv, wo_w, mlp1_w, mlp2_w, conv_w, bh, bl);
    }

    im2col_kernel<<<(int)(((long long)MPATCH * DVAL + 255) / 256), 256>>>(x);
    launch_hs(2, MPATCH, DVAL, DVAL, colp, DVAL, bh + OFF_WT, bl + OFF_WT, DVAL, ctxp, DVAL, conv_b);
    assemble_tok_kernel<<<(int)(((long long)MTOK * DVAL + 255) / 256), 256>>>(ctxp, cls_token, pos_embed);

    const long long DQ = (long long)DVAL * QKVN;
    const long long D2 = (long long)DVAL * DVAL;
    const long long DM = (long long)DVAL * MLPD;
    const long long SCS = (long long)NTOK * SCLD;

    for (int L = 0; L < DEPTH; L++) {
        ln_kernel<<<MTOK, 256>>>(tokp, hp, ln1_w + L * DVAL, ln1_b + L * DVAL);
        // fused QKV GEMM: [6304, 2304]
        launch_hs(0, MTOK, QKVN, DVAL, hp, DVAL,
                  bh + OFF_QKV + L * DQ, bl + OFF_QKV + L * DQ, QKVN, qkvp, QKVN, nullptr);

        // scores = Q @ K^T (128x128 tiles, padded ld=208)
        {
            dim3 grid((NTOK + 127) / 128, (NTOK + 127) / 128, BVAL * HEADS);
            scores_gemm<<<grid, 256>>>(NTOK, NTOK, DKV,
                qkvp,             QKVN, (long long)NTOK * QKVN, DKV,
                qkvp + DVAL,      QKVN, (long long)NTOK * QKVN, DKV,
                scp,              SCLD, (long long)HEADS * SCS, SCS,
                HEADS);
        }
        softmax_kernel<<<(BVAL * HEADS * NTOK + 7) / 8, 256>>>(scp);
        // ctx = attn @ V (vectorized A over padded K=208)
        {
            dim3 grid(1, (NTOK + 127) / 128, BVAL * HEADS);
            ctx_gemm<<<grid, 256>>>(NTOK, DKV,
                scp,              (long long)HEADS * SCS, SCS,
                qkvp + 2 * DVAL,  QKVN, (long long)NTOK * QKVN, DKV,
                ctxp,             DVAL, (long long)NTOK * DVAL, DKV,
                HEADS);
        }
        // tok += ctx @ Wo + bo   (split-K x4, atomic combine)
        launch_hs(5, MTOK, DVAL, DVAL, ctxp, DVAL,
                  bh + OFF_WO + L * D2, bl + OFF_WO + L * D2, DVAL, tokp, DVAL,
                  wo_b + L * DVAL, 4);
        ln_kernel<<<MTOK, 256>>>(tokp, hp, ln2_w + L * DVAL, ln2_b + L * DVAL);
        // hid = gelu(h @ W1 + b1)
        launch_hs(2, MTOK, MLPD, DVAL, hp, DVAL,
                  bh + OFF_M1 + L * DM, bl + OFF_M1 + L * DM, MLPD, hidp, MLPD, mlp1_b + L * MLPD);
        // tok += hid @ W2 + b2   (split-K x4, atomic combine)
        launch_hs(5, MTOK, DVAL, MLPD, hidp, MLPD,
                  bh + OFF_M2 + L * DM, bl + OFF_M2 + L * DM, DVAL, tokp, DVAL,
                  mlp2_b + L * DVAL, 4);
    }

    head_kernel<<<BVAL, 256>>>(tokp, fnorm_w, fnorm_b, hln_w, hln_b,
                               h1_w, h1_b, h2_w, h2_b, (float*)d_out);
}